// round 9
// baseline (speedup 1.0000x reference)
#include <cuda_runtime.h>

#define Dv 128
#define Hv 128
#define Wv 128
#define VOX (Dv*Hv*Wv)
#define NV4 (VOX/4)
#define NSL 16
#define NPIX (NSL*128*128)
#define NIT 10

// Staging box (per 16x16 pixel tile) — dynamic smem (48 KB -> 4 blocks/SM)
// Used FIRST as the gather source (volume subtile, zero-filled at edges),
// THEN re-zeroed and used as the scatter accumulator.
#define BX 32
#define BY 32
#define BZ 12
#define BVOL (BX*BY*BZ)
#define APPLY_THREADS 256

// Scratch (device globals: no runtime allocation allowed)
__device__ float g_x[VOX];
__device__ float g_r[VOX];
__device__ float g_p[VOX];
__device__ float g_Ap[VOX];
__device__ double g_rr[NIT + 1];
__device__ double g_pAp[NIT];
__device__ int g_bar_count = 0;
__device__ int g_bar_gen = 0;

__constant__ float c_psf[27];

// ---------------------------------------------------------------------------
// Guarded trilinear gather / scatter (fallback for non-fitting tiles; exact)
// ---------------------------------------------------------------------------
__device__ __forceinline__ float trigather_safe(const float* __restrict__ vol,
                                                float px, float py, float pz) {
    if (px <= -1.f || py <= -1.f || pz <= -1.f ||
        px >= (float)Wv || py >= (float)Hv || pz >= (float)Dv) return 0.f;
    float xf = floorf(px), yf = floorf(py), zf = floorf(pz);
    int ix = (int)xf, iy = (int)yf, iz = (int)zf;
    float fx = px - xf, fy = py - yf, fz = pz - zf;
    float gx = 1.f - fx, gy = 1.f - fy, gz = 1.f - fz;
    float s = 0.f;
    #pragma unroll
    for (int dz = 0; dz < 2; dz++)
    #pragma unroll
    for (int dy = 0; dy < 2; dy++)
    #pragma unroll
    for (int dx = 0; dx < 2; dx++) {
        int xi = ix + dx, yi = iy + dy, zi = iz + dz;
        if ((unsigned)xi < (unsigned)Wv && (unsigned)yi < (unsigned)Hv &&
            (unsigned)zi < (unsigned)Dv) {
            float wt = (dx ? fx : gx) * (dy ? fy : gy) * (dz ? fz : gz);
            s += wt * __ldg(vol + (zi * Hv + yi) * Wv + xi);
        }
    }
    return s;
}

__device__ __forceinline__ void triscatter_safe(float* __restrict__ vol,
                                                float px, float py, float pz, float val) {
    if (px <= -1.f || py <= -1.f || pz <= -1.f ||
        px >= (float)Wv || py >= (float)Hv || pz >= (float)Dv) return;
    float xf = floorf(px), yf = floorf(py), zf = floorf(pz);
    int ix = (int)xf, iy = (int)yf, iz = (int)zf;
    float fx = px - xf, fy = py - yf, fz = pz - zf;
    float gx = 1.f - fx, gy = 1.f - fy, gz = 1.f - fz;
    #pragma unroll
    for (int dz = 0; dz < 2; dz++)
    #pragma unroll
    for (int dy = 0; dy < 2; dy++)
    #pragma unroll
    for (int dx = 0; dx < 2; dx++) {
        int xi = ix + dx, yi = iy + dy, zi = iz + dz;
        if ((unsigned)xi < (unsigned)Wv && (unsigned)yi < (unsigned)Hv &&
            (unsigned)zi < (unsigned)Dv) {
            float wt = (dx ? fx : gx) * (dy ? fy : gy) * (dz ? fz : gz);
            atomicAdd(vol + (zi * Hv + yi) * Wv + xi, wt * val);
        }
    }
}

// Trilinear gather from the smem box (zero-filled OOB => exact semantics).
__device__ __forceinline__ float trigather_box(const float* __restrict__ sbox,
                                               float px, float py, float pz,
                                               int bx0, int by0, int bz0) {
    float xf = floorf(px), yf = floorf(py), zf = floorf(pz);
    int ix = (int)xf - bx0, iy = (int)yf - by0, iz = (int)zf - bz0;
    float fx = px - xf, fy = py - yf, fz = pz - zf;
    float gx = 1.f - fx, gy = 1.f - fy, gz = 1.f - fz;
    const float* q = sbox + (iz * BY + iy) * BX + ix;
    float v000 = q[0],       v001 = q[1];
    float v010 = q[BX],      v011 = q[BX + 1];
    const float* q2 = q + BY * BX;
    float v100 = q2[0],      v101 = q2[1];
    float v110 = q2[BX],     v111 = q2[BX + 1];
    float s0 = (v000 * gx + v001 * fx) * gy + (v010 * gx + v011 * fx) * fy;
    float s1 = (v100 * gx + v101 * fx) * gy + (v110 * gx + v111 * fx) * fy;
    return s0 * gz + s1 * fz;
}

// ---------------------------------------------------------------------------
// Block reduce + single atomic
// ---------------------------------------------------------------------------
template <int NWARP>
__device__ __forceinline__ void block_reduce_add(double v, double* dst) {
    #pragma unroll
    for (int o = 16; o; o >>= 1) v += __shfl_down_sync(0xffffffffu, v, o);
    __shared__ double sh[NWARP];
    int lane = threadIdx.x & 31, wid = threadIdx.x >> 5;
    if (lane == 0) sh[wid] = v;
    __syncthreads();
    if (wid == 0) {
        v = (lane < NWARP) ? sh[lane] : 0.0;
        #pragma unroll
        for (int o = NWARP / 2; o; o >>= 1) v += __shfl_down_sync(0xffffffffu, v, o);
        if (lane == 0) atomicAdd(dst, v);
    }
}

// ---------------------------------------------------------------------------
// Software grid barrier
// ---------------------------------------------------------------------------
__device__ __forceinline__ void grid_barrier(int nblocks) {
    __syncthreads();
    if (threadIdx.x == 0) {
        __threadfence();
        int my_gen = *(volatile int*)&g_bar_gen;
        int ticket = atomicAdd(&g_bar_count, 1);
        if (ticket == nblocks - 1) {
            g_bar_count = 0;
            __threadfence();
            atomicAdd(&g_bar_gen, 1);
        } else {
            while (*(volatile int*)&g_bar_gen == my_gen) { }
        }
        __threadfence();
    }
    __syncthreads();
}

// ---------------------------------------------------------------------------
// Fused apply. Block = 16x16 pixel tile, 256 threads, smem box 32x32x12.
// Fit path: box-load(gather src) -> smem gather -> re-zero -> smem scatter -> flush.
// INIT:  s = slices[pix] - A(x)[pix]; scatter psf*s into g_r.
// ITER:  s = A(p)[pix]; scatter psf*s into g_Ap; reduce sum(s^2) = p.AtAp.
// ---------------------------------------------------------------------------
template <bool INIT>
__global__ void __launch_bounds__(APPLY_THREADS, 4) apply_kernel(
    const float* __restrict__ theta,
    const float* __restrict__ vin, const float* __restrict__ src,
    float* __restrict__ vout, double* __restrict__ dot_dst)
{
    extern __shared__ __align__(16) float sbox[];

    int b = blockIdx.x;
    int n   = b >> 6;                  // 64 tiles per slice
    int tyx = b & 63;
    int ty0 = (tyx >> 3) << 4;         // tile row * 16
    int tx0 = (tyx & 7) << 4;          // tile col * 16
    int lx = threadIdx.x & 15, ly = threadIdx.x >> 4;
    int w = tx0 + lx, h = ty0 + ly;
    int pix = (n << 14) + (h << 7) + w;

    const float* T = theta + n * 12;
    float R00 = __ldg(T + 0), R01 = __ldg(T + 1),  R02 = __ldg(T + 2),  t0 = __ldg(T + 3);
    float R10 = __ldg(T + 4), R11 = __ldg(T + 5),  R12 = __ldg(T + 6),  t1 = __ldg(T + 7);
    float R20 = __ldg(T + 8), R21 = __ldg(T + 9),  R22 = __ldg(T + 10), t2 = __ldg(T + 11);

    float u = ((float)w - 63.5f) * 1.5f;
    float v = ((float)h - 63.5f) * 1.5f;
    float cx = R00 * u + R01 * v + t0 + 63.5f;
    float cy = R10 * u + R11 * v + t1 + 63.5f;
    float cz = R20 * u + R21 * v + t2 + 63.5f;

    float a0 = fabsf(R00) + fabsf(R01) + fabsf(R02);
    float a1 = fabsf(R10) + fabsf(R11) + fabsf(R12);
    float a2 = fabsf(R20) + fabsf(R21) + fabsf(R22);

    // uniform tile bounding box of all sample points (+trilinear corner)
    float u0 = ((float)tx0 - 63.5f) * 1.5f;
    float v0 = ((float)ty0 - 63.5f) * 1.5f;
    float X00 = R00 * u0 + R01 * v0 + t0 + 63.5f;
    float Y00 = R10 * u0 + R11 * v0 + t1 + 63.5f;
    float Z00 = R20 * u0 + R21 * v0 + t2 + 63.5f;
    const float SI = 22.5f, SJ = 22.5f;
    float eps = 0.01f;
    float mnx = X00 + fminf(0.f, SI * R00) + fminf(0.f, SJ * R01) - a0 - eps;
    float mxx = X00 + fmaxf(0.f, SI * R00) + fmaxf(0.f, SJ * R01) + a0 + eps;
    float mny = Y00 + fminf(0.f, SI * R10) + fminf(0.f, SJ * R11) - a1 - eps;
    float mxy = Y00 + fmaxf(0.f, SI * R10) + fmaxf(0.f, SJ * R11) + a1 + eps;
    float mnz = Z00 + fminf(0.f, SI * R20) + fminf(0.f, SJ * R21) - a2 - eps;
    float mxz = Z00 + fmaxf(0.f, SI * R20) + fmaxf(0.f, SJ * R21) + a2 + eps;
    int bx0 = (int)floorf(mnx), bx1 = (int)floorf(mxx) + 1;
    int by0 = (int)floorf(mny), by1 = (int)floorf(mxy) + 1;
    int bz0 = (int)floorf(mnz), bz1 = (int)floorf(mxz) + 1;

    // whole-tile footprint outside volume -> zero contribution everywhere
    if (bx1 < 0 || bx0 > Wv - 1 || by1 < 0 || by0 > Hv - 1 || bz1 < 0 || bz0 > Dv - 1)
        return;

    bool fit = (bx1 - bx0 < BX) && (by1 - by0 < BY) && (bz1 - bz0 < BZ);
    int nzp = min(bz1 - bz0 + 2, BZ);
    int ncell = nzp * (BY * BX);

    float s = 0.f;

    if (fit) {
        // ---- phase 1: load gather source box (zero-filled outside volume) ----
        for (int i = threadIdx.x; i < ncell; i += APPLY_THREADS) {
            int gx = bx0 + (i & (BX - 1));
            int gy = by0 + ((i >> 5) & (BY - 1));
            int gz = bz0 + (i >> 10);
            float val = 0.f;
            if ((unsigned)gx < (unsigned)Wv && (unsigned)gy < (unsigned)Hv &&
                (unsigned)gz < (unsigned)Dv)
                val = __ldg(vin + ((gz * Hv + gy) << 7) + gx);
            sbox[i] = val;
        }
        __syncthreads();

        // ---- phase 2: gather all 27 samples from smem ----
        float sA = 0.f, sB = 0.f;
        #pragma unroll
        for (int dz = 0; dz < 3; dz++) {
            float zx = cx + (float)(dz - 1) * R02;
            float zy = cy + (float)(dz - 1) * R12;
            float zz = cz + (float)(dz - 1) * R22;
            #pragma unroll
            for (int dy = 0; dy < 3; dy++) {
                float yx = zx + (float)(dy - 1) * R01;
                float yy = zy + (float)(dy - 1) * R11;
                float yz = zz + (float)(dy - 1) * R21;
                #pragma unroll
                for (int dx = 0; dx < 3; dx++) {
                    float px = yx + (float)(dx - 1) * R00;
                    float py = yy + (float)(dx - 1) * R10;
                    float pz = yz + (float)(dx - 1) * R20;
                    float g = c_psf[(dz * 3 + dy) * 3 + dx] *
                              trigather_box(sbox, px, py, pz, bx0, by0, bz0);
                    if (((dz * 3 + dy) * 3 + dx) & 1) sA += g; else sB += g;
                }
            }
        }
        s = sA + sB;

        if (INIT) {
            s = __ldg(src + pix) - s;
        } else {
            block_reduce_add<8>((double)s * (double)s, dot_dst);
        }

        // ---- phase 3: re-zero box for scatter staging ----
        __syncthreads();   // all gather reads done
        {
            float4* s4 = (float4*)sbox;
            float4 z4 = make_float4(0.f, 0.f, 0.f, 0.f);
            int n4 = ncell >> 2;
            for (int i = threadIdx.x; i < n4; i += APPLY_THREADS)
                s4[i] = z4;
        }
        __syncthreads();

        // ---- phase 4: scatter into smem box ----
        if (s != 0.f) {
            #pragma unroll
            for (int dz = 0; dz < 3; dz++) {
                float zx = cx + (float)(dz - 1) * R02;
                float zy = cy + (float)(dz - 1) * R12;
                float zz = cz + (float)(dz - 1) * R22;
                #pragma unroll
                for (int dy = 0; dy < 3; dy++) {
                    float yx = zx + (float)(dy - 1) * R01;
                    float yy = zy + (float)(dy - 1) * R11;
                    float yz = zz + (float)(dy - 1) * R21;
                    #pragma unroll
                    for (int dx = 0; dx < 3; dx++) {
                        float px = yx + (float)(dx - 1) * R00;
                        float py = yy + (float)(dx - 1) * R10;
                        float pz = yz + (float)(dx - 1) * R20;
                        float val = c_psf[(dz * 3 + dy) * 3 + dx] * s;
                        float xf = floorf(px), yf = floorf(py), zf = floorf(pz);
                        int ix = (int)xf - bx0, iy = (int)yf - by0, iz = (int)zf - bz0;
                        float fx = px - xf, fy = py - yf, fz = pz - zf;
                        float gx = 1.f - fx, gy = 1.f - fy, gz = 1.f - fz;
                        float* q = sbox + (iz * BY + iy) * BX + ix;
                        float w0 = val * gz, w1 = val * fz;
                        float gxgy = gx * gy, fxgy = fx * gy;
                        float gxfy = gx * fy, fxfy = fx * fy;
                        atomicAdd(q,              gxgy * w0);
                        atomicAdd(q + 1,          fxgy * w0);
                        atomicAdd(q + BX,         gxfy * w0);
                        atomicAdd(q + BX + 1,     fxfy * w0);
                        float* q2 = q + BY * BX;
                        atomicAdd(q2,             gxgy * w1);
                        atomicAdd(q2 + 1,         fxgy * w1);
                        atomicAdd(q2 + BX,        gxfy * w1);
                        atomicAdd(q2 + BX + 1,    fxfy * w1);
                    }
                }
            }
        }
        __syncthreads();

        // ---- phase 5: clipped flush ----
        for (int i = threadIdx.x; i < ncell; i += APPLY_THREADS) {
            float val = sbox[i];
            if (val != 0.f) {
                int gx = bx0 + (i & (BX - 1));
                int gy = by0 + ((i >> 5) & (BY - 1));
                int gz = bz0 + (i >> 10);
                if ((unsigned)gx < (unsigned)Wv && (unsigned)gy < (unsigned)Hv &&
                    (unsigned)gz < (unsigned)Dv)
                    atomicAdd(vout + ((gz * Hv + gy) << 7) + gx, val);
            }
        }
    } else {
        // ---- fallback: direct global safe gather/scatter ----
        bool fully_out =
            (cx + a0 <= -1.001f) || (cx - a0 >= 128.001f) ||
            (cy + a1 <= -1.001f) || (cy - a1 >= 128.001f) ||
            (cz + a2 <= -1.001f) || (cz - a2 >= 128.001f);
        if (!fully_out) {
            #pragma unroll 3
            for (int k = 0; k < 27; k++) {
                float ox = (float)(k % 3 - 1);
                float oy = (float)((k / 3) % 3 - 1);
                float oz = (float)(k / 9 - 1);
                float px = cx + ox * R00 + oy * R01 + oz * R02;
                float py = cy + ox * R10 + oy * R11 + oz * R12;
                float pz = cz + ox * R20 + oy * R21 + oz * R22;
                s += c_psf[k] * trigather_safe(vin, px, py, pz);
            }
        }
        if (INIT) {
            s = __ldg(src + pix) - s;
        } else {
            block_reduce_add<8>((double)s * (double)s, dot_dst);
        }
        if (!fully_out && s != 0.f) {
            #pragma unroll 3
            for (int k = 0; k < 27; k++) {
                float ox = (float)(k % 3 - 1);
                float oy = (float)((k / 3) % 3 - 1);
                float oz = (float)(k / 9 - 1);
                float px = cx + ox * R00 + oy * R01 + oz * R02;
                float py = cy + ox * R10 + oy * R11 + oz * R12;
                float pz = cz + ox * R20 + oy * R21 + oz * R22;
                triscatter_safe(vout, px, py, pz, c_psf[k] * s);
            }
        }
    }
}

// ---------------------------------------------------------------------------
// Vectorized CG plumbing: float4, 512 blocks x 256 threads, fixed 4-iter unroll.
// ---------------------------------------------------------------------------
#define VGRID 512
#define VTHREADS 256
#define VSTRIDE (VGRID * VTHREADS)

__global__ void __launch_bounds__(VTHREADS) setup_kernel(const float4* __restrict__ vol) {
    int i = blockIdx.x * VTHREADS + threadIdx.x;
    float4 z = make_float4(0.f, 0.f, 0.f, 0.f);
    float4* r4 = (float4*)g_r;
    float4* x4 = (float4*)g_x;
    #pragma unroll
    for (int k = 0; k < 4; k++) {
        int j = i + k * VSTRIDE;
        r4[j] = z;
        x4[j] = vol[j];
    }
    if (i < NIT + 1) g_rr[i] = 0.0;
    if (i >= 64 && i < 64 + NIT) g_pAp[i - 64] = 0.0;
}

__global__ void __launch_bounds__(VTHREADS) init_r_kernel() {
    int i = blockIdx.x * VTHREADS + threadIdx.x;
    const float4* r4 = (const float4*)g_r;
    float4* p4  = (float4*)g_p;
    float4* ap4 = (float4*)g_Ap;
    float4 z = make_float4(0.f, 0.f, 0.f, 0.f);
    double acc = 0.0;
    #pragma unroll
    for (int k = 0; k < 4; k++) {
        int j = i + k * VSTRIDE;
        float4 rv = r4[j];
        p4[j] = rv;
        ap4[j] = z;
        acc += (double)rv.x * rv.x + (double)rv.y * rv.y +
               (double)rv.z * rv.z + (double)rv.w * rv.w;
    }
    block_reduce_add<8>(acc, &g_rr[0]);
}

// Fused update: phase1 (x,r,rr reduce) -> grid barrier -> phase2 (beta, p, Ap=0)
__global__ void __launch_bounds__(VTHREADS) fused_update_kernel(int it) {
    __shared__ float s_alpha;
    if (threadIdx.x == 0) s_alpha = (float)(g_rr[it] / g_pAp[it]);
    __syncthreads();
    float alpha = s_alpha;
    int i = blockIdx.x * VTHREADS + threadIdx.x;
    float4* x4  = (float4*)g_x;
    float4* r4  = (float4*)g_r;
    float4* p4  = (float4*)g_p;
    float4* ap4 = (float4*)g_Ap;
    double acc = 0.0;
    float4 rloc[4];
    #pragma unroll
    for (int k = 0; k < 4; k++) {
        int j = i + k * VSTRIDE;
        float4 x = x4[j], p = p4[j], r = r4[j], a = ap4[j];
        x.x += alpha * p.x; x.y += alpha * p.y; x.z += alpha * p.z; x.w += alpha * p.w;
        r.x -= alpha * a.x; r.y -= alpha * a.y; r.z -= alpha * a.z; r.w -= alpha * a.w;
        x4[j] = x;
        r4[j] = r;
        rloc[k] = r;
        acc += (double)r.x * r.x + (double)r.y * r.y +
               (double)r.z * r.z + (double)r.w * r.w;
    }
    block_reduce_add<8>(acc, &g_rr[it + 1]);

    grid_barrier(VGRID);

    __shared__ float s_beta;
    if (threadIdx.x == 0) {
        double rrn = *(volatile double*)&g_rr[it + 1];
        s_beta = (float)(rrn / g_rr[it]);
    }
    __syncthreads();
    float beta = s_beta;
    float4 z = make_float4(0.f, 0.f, 0.f, 0.f);
    #pragma unroll
    for (int k = 0; k < 4; k++) {
        int j = i + k * VSTRIDE;
        float4 r = rloc[k], p = p4[j];
        p.x = r.x + beta * p.x; p.y = r.y + beta * p.y;
        p.z = r.z + beta * p.z; p.w = r.w + beta * p.w;
        p4[j] = p;
        ap4[j] = z;
    }
}

__global__ void __launch_bounds__(VTHREADS) final_kernel(float4* __restrict__ out) {
    __shared__ float s_alpha;
    if (threadIdx.x == 0) s_alpha = (float)(g_rr[NIT - 1] / g_pAp[NIT - 1]);
    __syncthreads();
    float alpha = s_alpha;
    int i = blockIdx.x * VTHREADS + threadIdx.x;
    const float4* x4 = (const float4*)g_x;
    const float4* p4 = (const float4*)g_p;
    #pragma unroll
    for (int k = 0; k < 4; k++) {
        int j = i + k * VSTRIDE;
        float4 x = x4[j], p = p4[j];
        out[j] = make_float4(fmaxf(x.x + alpha * p.x, 0.f),
                             fmaxf(x.y + alpha * p.y, 0.f),
                             fmaxf(x.z + alpha * p.z, 0.f),
                             fmaxf(x.w + alpha * p.w, 0.f));
    }
}

// ---------------------------------------------------------------------------
// Launch
// ---------------------------------------------------------------------------
extern "C" void kernel_launch(void* const* d_in, const int* in_sizes, int n_in,
                              void* d_out, int out_size) {
    const float *theta = nullptr, *slices = nullptr, *volume = nullptr, *psf = nullptr;
    for (int i = 0; i < n_in; i++) {
        switch (in_sizes[i]) {
            case 192:     theta  = (const float*)d_in[i]; break;
            case 262144:  slices = (const float*)d_in[i]; break;
            case 2097152: volume = (const float*)d_in[i]; break;
            case 27:      psf    = (const float*)d_in[i]; break;
        }
    }

    const int SBYTES = BVOL * (int)sizeof(float);   // 49152

    static float* pr  = nullptr;
    static float* pp  = nullptr;
    static float* px_ = nullptr;
    static float* pAp = nullptr;
    static double* ppAp = nullptr;
    if (!pr) {
        cudaGetSymbolAddress((void**)&pr,   g_r);
        cudaGetSymbolAddress((void**)&pp,   g_p);
        cudaGetSymbolAddress((void**)&px_,  g_x);
        cudaGetSymbolAddress((void**)&pAp,  g_Ap);
        cudaGetSymbolAddress((void**)&ppAp, g_pAp);
        cudaFuncSetAttribute(apply_kernel<true>,
                             cudaFuncAttributeMaxDynamicSharedMemorySize, SBYTES);
        cudaFuncSetAttribute(apply_kernel<false>,
                             cudaFuncAttributeMaxDynamicSharedMemorySize, SBYTES);
    }

    const int PB = NPIX / 256;   // 1024 tile blocks (16x16 tiles)

    // psf -> constant memory (D2D async copy; graph-capturable)
    cudaMemcpyToSymbolAsync(c_psf, psf, 27 * sizeof(float), 0,
                            cudaMemcpyDeviceToDevice, 0);

    setup_kernel<<<VGRID, VTHREADS>>>((const float4*)volume);
    // r0 = At(slices - A x0), scattered directly into g_r
    apply_kernel<true><<<PB, APPLY_THREADS, SBYTES>>>(theta, px_, slices, pr, nullptr);
    // p = r; Ap = 0; rr0
    init_r_kernel<<<VGRID, VTHREADS>>>();

    for (int it = 0; it < NIT; it++) {
        // Ap = AtA(p); pAp = sum(s^2)
        apply_kernel<false><<<PB, APPLY_THREADS, SBYTES>>>(theta, pp, nullptr, pAp, ppAp + it);
        if (it == NIT - 1) {
            final_kernel<<<VGRID, VTHREADS>>>((float4*)d_out);
        } else {
            fused_update_kernel<<<VGRID, VTHREADS>>>(it);
        }
    }
}

// round 10
// speedup vs baseline: 1.1274x; 1.1274x over previous
#include <cuda_runtime.h>

#define Dv 128
#define Hv 128
#define Wv 128
#define VOX (Dv*Hv*Wv)
#define NV4 (VOX/4)
#define NSL 16
#define NPIX (NSL*128*128)
#define NIT 10

// Scatter staging box (per 16x16 pixel tile) — dynamic smem (48 KB)
#define BX 32
#define BY 32
#define BZ 12
#define BVOL (BX*BY*BZ)
#define APPLY_THREADS 256

// Scratch (device globals: no runtime allocation allowed)
__device__ float g_x[VOX];
__device__ float g_r[VOX];
__device__ float g_p[VOX];
__device__ float g_Ap[VOX];
__device__ double g_rr[NIT + 1];
__device__ double g_pAp[NIT];
__device__ int g_bar_count = 0;
__device__ int g_bar_gen = 0;

__constant__ float c_psf[27];

// ---------------------------------------------------------------------------
// Guarded trilinear gather / scatter (boundary/fallback; match reference)
// ---------------------------------------------------------------------------
__device__ __forceinline__ float trigather_safe(const float* __restrict__ vol,
                                                float px, float py, float pz) {
    if (px <= -1.f || py <= -1.f || pz <= -1.f ||
        px >= (float)Wv || py >= (float)Hv || pz >= (float)Dv) return 0.f;
    float xf = floorf(px), yf = floorf(py), zf = floorf(pz);
    int ix = (int)xf, iy = (int)yf, iz = (int)zf;
    float fx = px - xf, fy = py - yf, fz = pz - zf;
    float gx = 1.f - fx, gy = 1.f - fy, gz = 1.f - fz;
    float s = 0.f;
    #pragma unroll
    for (int dz = 0; dz < 2; dz++)
    #pragma unroll
    for (int dy = 0; dy < 2; dy++)
    #pragma unroll
    for (int dx = 0; dx < 2; dx++) {
        int xi = ix + dx, yi = iy + dy, zi = iz + dz;
        if ((unsigned)xi < (unsigned)Wv && (unsigned)yi < (unsigned)Hv &&
            (unsigned)zi < (unsigned)Dv) {
            float wt = (dx ? fx : gx) * (dy ? fy : gy) * (dz ? fz : gz);
            s += wt * __ldg(vol + (zi * Hv + yi) * Wv + xi);
        }
    }
    return s;
}

__device__ __forceinline__ void triscatter_safe(float* __restrict__ vol,
                                                float px, float py, float pz, float val) {
    if (px <= -1.f || py <= -1.f || pz <= -1.f ||
        px >= (float)Wv || py >= (float)Hv || pz >= (float)Dv) return;
    float xf = floorf(px), yf = floorf(py), zf = floorf(pz);
    int ix = (int)xf, iy = (int)yf, iz = (int)zf;
    float fx = px - xf, fy = py - yf, fz = pz - zf;
    float gx = 1.f - fx, gy = 1.f - fy, gz = 1.f - fz;
    #pragma unroll
    for (int dz = 0; dz < 2; dz++)
    #pragma unroll
    for (int dy = 0; dy < 2; dy++)
    #pragma unroll
    for (int dx = 0; dx < 2; dx++) {
        int xi = ix + dx, yi = iy + dy, zi = iz + dz;
        if ((unsigned)xi < (unsigned)Wv && (unsigned)yi < (unsigned)Hv &&
            (unsigned)zi < (unsigned)Dv) {
            float wt = (dx ? fx : gx) * (dy ? fy : gy) * (dz ? fz : gz);
            atomicAdd(vol + (zi * Hv + yi) * Wv + xi, wt * val);
        }
    }
}

__device__ __forceinline__ float trigather_fast(const float* __restrict__ vol,
                                                float px, float py, float pz) {
    float xf = floorf(px), yf = floorf(py), zf = floorf(pz);
    int ix = (int)xf, iy = (int)yf, iz = (int)zf;
    float fx = px - xf, fy = py - yf, fz = pz - zf;
    float gx = 1.f - fx, gy = 1.f - fy, gz = 1.f - fz;
    const float* q = vol + ((iz * Hv + iy) << 7) + ix;
    float v000 = __ldg(q),        v001 = __ldg(q + 1);
    float v010 = __ldg(q + Wv),   v011 = __ldg(q + Wv + 1);
    const float* q2 = q + Hv * Wv;
    float v100 = __ldg(q2),       v101 = __ldg(q2 + 1);
    float v110 = __ldg(q2 + Wv),  v111 = __ldg(q2 + Wv + 1);
    float s0 = (v000 * gx + v001 * fx) * gy + (v010 * gx + v011 * fx) * fy;
    float s1 = (v100 * gx + v101 * fx) * gy + (v110 * gx + v111 * fx) * fy;
    return s0 * gz + s1 * fz;
}

// ---------------------------------------------------------------------------
// Block reduce + single atomic
// ---------------------------------------------------------------------------
template <int NWARP>
__device__ __forceinline__ void block_reduce_add(double v, double* dst) {
    #pragma unroll
    for (int o = 16; o; o >>= 1) v += __shfl_down_sync(0xffffffffu, v, o);
    __shared__ double sh[NWARP];
    int lane = threadIdx.x & 31, wid = threadIdx.x >> 5;
    if (lane == 0) sh[wid] = v;
    __syncthreads();
    if (wid == 0) {
        v = (lane < NWARP) ? sh[lane] : 0.0;
        #pragma unroll
        for (int o = NWARP / 2; o; o >>= 1) v += __shfl_down_sync(0xffffffffu, v, o);
        if (lane == 0) atomicAdd(dst, v);
    }
}

// ---------------------------------------------------------------------------
// Software grid barrier
// ---------------------------------------------------------------------------
__device__ __forceinline__ void grid_barrier(int nblocks) {
    __syncthreads();
    if (threadIdx.x == 0) {
        __threadfence();
        int my_gen = *(volatile int*)&g_bar_gen;
        int ticket = atomicAdd(&g_bar_count, 1);
        if (ticket == nblocks - 1) {
            g_bar_count = 0;
            __threadfence();
            atomicAdd(&g_bar_gen, 1);
        } else {
            while (*(volatile int*)&g_bar_gen == my_gen) { }
        }
        __threadfence();
    }
    __syncthreads();
}

// ---------------------------------------------------------------------------
// Shared pixel/tile geometry setup
// ---------------------------------------------------------------------------
struct TileGeom {
    float cx, cy, cz, a0, a1, a2;
    float R00, R01, R02, R10, R11, R12, R20, R21, R22;
    int pix;
    int bx0, bx1, by0, by1, bz0, bz1;
    bool tile_out;
};

__device__ __forceinline__ TileGeom tile_geom(const float* __restrict__ theta, int b) {
    TileGeom G;
    int n   = b >> 6;                  // 64 tiles per slice
    int tyx = b & 63;
    int ty0 = (tyx >> 3) << 4;
    int tx0 = (tyx & 7) << 4;
    int lx = threadIdx.x & 15, ly = threadIdx.x >> 4;
    int w = tx0 + lx, h = ty0 + ly;
    G.pix = (n << 14) + (h << 7) + w;

    const float* T = theta + n * 12;
    G.R00 = __ldg(T + 0); G.R01 = __ldg(T + 1);  G.R02 = __ldg(T + 2);  float t0 = __ldg(T + 3);
    G.R10 = __ldg(T + 4); G.R11 = __ldg(T + 5);  G.R12 = __ldg(T + 6);  float t1 = __ldg(T + 7);
    G.R20 = __ldg(T + 8); G.R21 = __ldg(T + 9);  G.R22 = __ldg(T + 10); float t2 = __ldg(T + 11);

    float u = ((float)w - 63.5f) * 1.5f;
    float v = ((float)h - 63.5f) * 1.5f;
    G.cx = G.R00 * u + G.R01 * v + t0 + 63.5f;
    G.cy = G.R10 * u + G.R11 * v + t1 + 63.5f;
    G.cz = G.R20 * u + G.R21 * v + t2 + 63.5f;
    G.a0 = fabsf(G.R00) + fabsf(G.R01) + fabsf(G.R02);
    G.a1 = fabsf(G.R10) + fabsf(G.R11) + fabsf(G.R12);
    G.a2 = fabsf(G.R20) + fabsf(G.R21) + fabsf(G.R22);

    float u0 = ((float)tx0 - 63.5f) * 1.5f;
    float v0 = ((float)ty0 - 63.5f) * 1.5f;
    float X00 = G.R00 * u0 + G.R01 * v0 + t0 + 63.5f;
    float Y00 = G.R10 * u0 + G.R11 * v0 + t1 + 63.5f;
    float Z00 = G.R20 * u0 + G.R21 * v0 + t2 + 63.5f;
    const float SI = 22.5f, SJ = 22.5f;
    float eps = 0.01f;
    float mnx = X00 + fminf(0.f, SI * G.R00) + fminf(0.f, SJ * G.R01) - G.a0 - eps;
    float mxx = X00 + fmaxf(0.f, SI * G.R00) + fmaxf(0.f, SJ * G.R01) + G.a0 + eps;
    float mny = Y00 + fminf(0.f, SI * G.R10) + fminf(0.f, SJ * G.R11) - G.a1 - eps;
    float mxy = Y00 + fmaxf(0.f, SI * G.R10) + fmaxf(0.f, SJ * G.R11) + G.a1 + eps;
    float mnz = Z00 + fminf(0.f, SI * G.R20) + fminf(0.f, SJ * G.R21) - G.a2 - eps;
    float mxz = Z00 + fmaxf(0.f, SI * G.R20) + fmaxf(0.f, SJ * G.R21) + G.a2 + eps;
    G.bx0 = (int)floorf(mnx); G.bx1 = (int)floorf(mxx) + 1;
    G.by0 = (int)floorf(mny); G.by1 = (int)floorf(mxy) + 1;
    G.bz0 = (int)floorf(mnz); G.bz1 = (int)floorf(mxz) + 1;
    G.tile_out = (G.bx1 < 0 || G.bx0 > Wv - 1 || G.by1 < 0 || G.by0 > Hv - 1 ||
                  G.bz1 < 0 || G.bz0 > Dv - 1);
    return G;
}

// Gather s = A(vin) at this pixel (interior fast path / guarded fallback).
__device__ __forceinline__ float gather_pixel(const TileGeom& G,
                                              const float* __restrict__ vin) {
    bool fully_out =
        (G.cx + G.a0 <= -1.001f) || (G.cx - G.a0 >= 128.001f) ||
        (G.cy + G.a1 <= -1.001f) || (G.cy - G.a1 >= 128.001f) ||
        (G.cz + G.a2 <= -1.001f) || (G.cz - G.a2 >= 128.001f);
    if (fully_out) return 0.f;
    bool interior =
        (G.cx - G.a0 >= 0.001f) && (G.cx + G.a0 <= 126.999f) &&
        (G.cy - G.a1 >= 0.001f) && (G.cy + G.a1 <= 126.999f) &&
        (G.cz - G.a2 >= 0.001f) && (G.cz + G.a2 <= 126.999f);
    float s = 0.f;
    if (interior) {
        float sA = 0.f, sB = 0.f;
        #pragma unroll
        for (int dz = 0; dz < 3; dz++) {
            float zx = G.cx + (float)(dz - 1) * G.R02;
            float zy = G.cy + (float)(dz - 1) * G.R12;
            float zz = G.cz + (float)(dz - 1) * G.R22;
            #pragma unroll
            for (int dy = 0; dy < 3; dy++) {
                float yx = zx + (float)(dy - 1) * G.R01;
                float yy = zy + (float)(dy - 1) * G.R11;
                float yz = zz + (float)(dy - 1) * G.R21;
                #pragma unroll
                for (int dx = 0; dx < 3; dx++) {
                    float px = yx + (float)(dx - 1) * G.R00;
                    float py = yy + (float)(dx - 1) * G.R10;
                    float pz = yz + (float)(dx - 1) * G.R20;
                    float g = c_psf[(dz * 3 + dy) * 3 + dx] *
                              trigather_fast(vin, px, py, pz);
                    if (((dz * 3 + dy) * 3 + dx) & 1) sA += g; else sB += g;
                }
            }
        }
        s = sA + sB;
    } else {
        #pragma unroll 3
        for (int k = 0; k < 27; k++) {
            float ox = (float)(k % 3 - 1);
            float oy = (float)((k / 3) % 3 - 1);
            float oz = (float)(k / 9 - 1);
            float px = G.cx + ox * G.R00 + oy * G.R01 + oz * G.R02;
            float py = G.cy + ox * G.R10 + oy * G.R11 + oz * G.R12;
            float pz = G.cz + ox * G.R20 + oy * G.R21 + oz * G.R22;
            s += c_psf[k] * trigather_safe(vin, px, py, pz);
        }
    }
    return s;
}

// ---------------------------------------------------------------------------
// Full apply (gather + scatter). R8-proven structure.
// INIT:  s = slices[pix] - A(x)[pix]; scatter psf*s into g_r.
// ITER:  s = A(p)[pix]; scatter psf*s into g_Ap; reduce sum(s^2) = p.AtAp.
// ---------------------------------------------------------------------------
template <bool INIT>
__global__ void __launch_bounds__(APPLY_THREADS, 4) apply_kernel(
    const float* __restrict__ theta,
    const float* __restrict__ vin, const float* __restrict__ src,
    float* __restrict__ vout, double* __restrict__ dot_dst)
{
    extern __shared__ __align__(16) float sbox[];

    TileGeom G = tile_geom(theta, blockIdx.x);
    if (G.tile_out) return;

    bool fit = (G.bx1 - G.bx0 < BX) && (G.by1 - G.by0 < BY) && (G.bz1 - G.bz0 < BZ);
    int nzp = min(G.bz1 - G.bz0 + 2, BZ);
    int ncell = nzp * (BY * BX);

    if (fit) {
        float4* s4 = (float4*)sbox;
        float4 z4 = make_float4(0.f, 0.f, 0.f, 0.f);
        int n4 = ncell >> 2;
        for (int i = threadIdx.x; i < n4; i += APPLY_THREADS)
            s4[i] = z4;
    }

    float s = gather_pixel(G, vin);

    if (INIT) {
        s = __ldg(src + G.pix) - s;
    } else {
        block_reduce_add<8>((double)s * (double)s, dot_dst);
    }

    if (fit) {
        __syncthreads();
        if (s != 0.f) {
            #pragma unroll
            for (int dz = 0; dz < 3; dz++) {
                float zx = G.cx + (float)(dz - 1) * G.R02;
                float zy = G.cy + (float)(dz - 1) * G.R12;
                float zz = G.cz + (float)(dz - 1) * G.R22;
                #pragma unroll
                for (int dy = 0; dy < 3; dy++) {
                    float yx = zx + (float)(dy - 1) * G.R01;
                    float yy = zy + (float)(dy - 1) * G.R11;
                    float yz = zz + (float)(dy - 1) * G.R21;
                    #pragma unroll
                    for (int dx = 0; dx < 3; dx++) {
                        float px = yx + (float)(dx - 1) * G.R00;
                        float py = yy + (float)(dx - 1) * G.R10;
                        float pz = yz + (float)(dx - 1) * G.R20;
                        float val = c_psf[(dz * 3 + dy) * 3 + dx] * s;
                        float xf = floorf(px), yf = floorf(py), zf = floorf(pz);
                        int ix = (int)xf - G.bx0, iy = (int)yf - G.by0, iz = (int)zf - G.bz0;
                        float fx = px - xf, fy = py - yf, fz = pz - zf;
                        float gx = 1.f - fx, gy = 1.f - fy, gz = 1.f - fz;
                        if ((unsigned)ix < BX - 1 && (unsigned)iy < BY - 1 &&
                            (unsigned)iz < BZ - 1) {
                            float* q = sbox + (iz * BY + iy) * BX + ix;
                            float w0 = val * gz, w1 = val * fz;
                            float gxgy = gx * gy, fxgy = fx * gy;
                            float gxfy = gx * fy, fxfy = fx * fy;
                            atomicAdd(q,              gxgy * w0);
                            atomicAdd(q + 1,          fxgy * w0);
                            atomicAdd(q + BX,         gxfy * w0);
                            atomicAdd(q + BX + 1,     fxfy * w0);
                            float* q2 = q + BY * BX;
                            atomicAdd(q2,             gxgy * w1);
                            atomicAdd(q2 + 1,         fxgy * w1);
                            atomicAdd(q2 + BX,        gxfy * w1);
                            atomicAdd(q2 + BX + 1,    fxfy * w1);
                        } else {
                            triscatter_safe(vout, px, py, pz, val);
                        }
                    }
                }
            }
        }
        __syncthreads();
        for (int i = threadIdx.x; i < ncell; i += APPLY_THREADS) {
            float val = sbox[i];
            if (val != 0.f) {
                int gx = G.bx0 + (i & (BX - 1));
                int gy = G.by0 + ((i >> 5) & (BY - 1));
                int gz = G.bz0 + (i >> 10);
                if ((unsigned)gx < (unsigned)Wv && (unsigned)gy < (unsigned)Hv &&
                    (unsigned)gz < (unsigned)Dv)
                    atomicAdd(vout + ((gz * Hv + gy) << 7) + gx, val);
            }
        }
    } else if (s != 0.f) {
        #pragma unroll 3
        for (int k = 0; k < 27; k++) {
            float ox = (float)(k % 3 - 1);
            float oy = (float)((k / 3) % 3 - 1);
            float oz = (float)(k / 9 - 1);
            float px = G.cx + ox * G.R00 + oy * G.R01 + oz * G.R02;
            float py = G.cy + ox * G.R10 + oy * G.R11 + oz * G.R12;
            float pz = G.cz + ox * G.R20 + oy * G.R21 + oz * G.R22;
            triscatter_safe(vout, px, py, pz, c_psf[k] * s);
        }
    }
}

// ---------------------------------------------------------------------------
// Gather-only dot kernel for the FINAL iteration: pAp = sum(A(p)^2).
// No smem box, no scatter => high occupancy, ~half the apply cost.
// ---------------------------------------------------------------------------
__global__ void __launch_bounds__(APPLY_THREADS) apply_dot_kernel(
    const float* __restrict__ theta, const float* __restrict__ vin,
    double* __restrict__ dot_dst)
{
    TileGeom G = tile_geom(theta, blockIdx.x);
    float s = G.tile_out ? 0.f : gather_pixel(G, vin);
    block_reduce_add<8>((double)s * (double)s, dot_dst);
}

// ---------------------------------------------------------------------------
// Vectorized CG plumbing: float4, 512 blocks x 256 threads, fixed 4-iter unroll.
// ---------------------------------------------------------------------------
#define VGRID 512
#define VTHREADS 256
#define VSTRIDE (VGRID * VTHREADS)

__global__ void __launch_bounds__(VTHREADS) setup_kernel(const float4* __restrict__ vol) {
    int i = blockIdx.x * VTHREADS + threadIdx.x;
    float4 z = make_float4(0.f, 0.f, 0.f, 0.f);
    float4* r4 = (float4*)g_r;
    float4* x4 = (float4*)g_x;
    #pragma unroll
    for (int k = 0; k < 4; k++) {
        int j = i + k * VSTRIDE;
        r4[j] = z;
        x4[j] = vol[j];
    }
    if (i < NIT + 1) g_rr[i] = 0.0;
    if (i >= 64 && i < 64 + NIT) g_pAp[i - 64] = 0.0;
}

__global__ void __launch_bounds__(VTHREADS) init_r_kernel() {
    int i = blockIdx.x * VTHREADS + threadIdx.x;
    const float4* r4 = (const float4*)g_r;
    float4* p4  = (float4*)g_p;
    float4* ap4 = (float4*)g_Ap;
    float4 z = make_float4(0.f, 0.f, 0.f, 0.f);
    double acc = 0.0;
    #pragma unroll
    for (int k = 0; k < 4; k++) {
        int j = i + k * VSTRIDE;
        float4 rv = r4[j];
        p4[j] = rv;
        ap4[j] = z;
        acc += (double)rv.x * rv.x + (double)rv.y * rv.y +
               (double)rv.z * rv.z + (double)rv.w * rv.w;
    }
    block_reduce_add<8>(acc, &g_rr[0]);
}

// Fused update: phase1 (x,r,rr reduce) -> grid barrier -> phase2 (beta, p, Ap=0)
__global__ void __launch_bounds__(VTHREADS) fused_update_kernel(int it) {
    __shared__ float s_alpha;
    if (threadIdx.x == 0) s_alpha = (float)(g_rr[it] / g_pAp[it]);
    __syncthreads();
    float alpha = s_alpha;
    int i = blockIdx.x * VTHREADS + threadIdx.x;
    float4* x4  = (float4*)g_x;
    float4* r4  = (float4*)g_r;
    float4* p4  = (float4*)g_p;
    float4* ap4 = (float4*)g_Ap;
    double acc = 0.0;
    float4 rloc[4];
    #pragma unroll
    for (int k = 0; k < 4; k++) {
        int j = i + k * VSTRIDE;
        float4 x = x4[j], p = p4[j], r = r4[j], a = ap4[j];
        x.x += alpha * p.x; x.y += alpha * p.y; x.z += alpha * p.z; x.w += alpha * p.w;
        r.x -= alpha * a.x; r.y -= alpha * a.y; r.z -= alpha * a.z; r.w -= alpha * a.w;
        x4[j] = x;
        r4[j] = r;
        rloc[k] = r;
        acc += (double)r.x * r.x + (double)r.y * r.y +
               (double)r.z * r.z + (double)r.w * r.w;
    }
    block_reduce_add<8>(acc, &g_rr[it + 1]);

    grid_barrier(VGRID);

    __shared__ float s_beta;
    if (threadIdx.x == 0) {
        double rrn = *(volatile double*)&g_rr[it + 1];
        s_beta = (float)(rrn / g_rr[it]);
    }
    __syncthreads();
    float beta = s_beta;
    float4 z = make_float4(0.f, 0.f, 0.f, 0.f);
    #pragma unroll
    for (int k = 0; k < 4; k++) {
        int j = i + k * VSTRIDE;
        float4 r = rloc[k], p = p4[j];
        p.x = r.x + beta * p.x; p.y = r.y + beta * p.y;
        p.z = r.z + beta * p.z; p.w = r.w + beta * p.w;
        p4[j] = p;
        ap4[j] = z;
    }
}

__global__ void __launch_bounds__(VTHREADS) final_kernel(float4* __restrict__ out) {
    __shared__ float s_alpha;
    if (threadIdx.x == 0) s_alpha = (float)(g_rr[NIT - 1] / g_pAp[NIT - 1]);
    __syncthreads();
    float alpha = s_alpha;
    int i = blockIdx.x * VTHREADS + threadIdx.x;
    const float4* x4 = (const float4*)g_x;
    const float4* p4 = (const float4*)g_p;
    #pragma unroll
    for (int k = 0; k < 4; k++) {
        int j = i + k * VSTRIDE;
        float4 x = x4[j], p = p4[j];
        out[j] = make_float4(fmaxf(x.x + alpha * p.x, 0.f),
                             fmaxf(x.y + alpha * p.y, 0.f),
                             fmaxf(x.z + alpha * p.z, 0.f),
                             fmaxf(x.w + alpha * p.w, 0.f));
    }
}

// ---------------------------------------------------------------------------
// Launch
// ---------------------------------------------------------------------------
extern "C" void kernel_launch(void* const* d_in, const int* in_sizes, int n_in,
                              void* d_out, int out_size) {
    const float *theta = nullptr, *slices = nullptr, *volume = nullptr, *psf = nullptr;
    for (int i = 0; i < n_in; i++) {
        switch (in_sizes[i]) {
            case 192:     theta  = (const float*)d_in[i]; break;
            case 262144:  slices = (const float*)d_in[i]; break;
            case 2097152: volume = (const float*)d_in[i]; break;
            case 27:      psf    = (const float*)d_in[i]; break;
        }
    }

    const int SBYTES = BVOL * (int)sizeof(float);   // 49152

    static float* pr  = nullptr;
    static float* pp  = nullptr;
    static float* px_ = nullptr;
    static float* pAp = nullptr;
    static double* ppAp = nullptr;
    if (!pr) {
        cudaGetSymbolAddress((void**)&pr,   g_r);
        cudaGetSymbolAddress((void**)&pp,   g_p);
        cudaGetSymbolAddress((void**)&px_,  g_x);
        cudaGetSymbolAddress((void**)&pAp,  g_Ap);
        cudaGetSymbolAddress((void**)&ppAp, g_pAp);
        cudaFuncSetAttribute(apply_kernel<true>,
                             cudaFuncAttributeMaxDynamicSharedMemorySize, SBYTES);
        cudaFuncSetAttribute(apply_kernel<false>,
                             cudaFuncAttributeMaxDynamicSharedMemorySize, SBYTES);
    }

    const int PB = NPIX / 256;   // 1024 tile blocks (16x16 tiles)

    // psf -> constant memory (D2D async copy; graph-capturable)
    cudaMemcpyToSymbolAsync(c_psf, psf, 27 * sizeof(float), 0,
                            cudaMemcpyDeviceToDevice, 0);

    setup_kernel<<<VGRID, VTHREADS>>>((const float4*)volume);
    // r0 = At(slices - A x0), scattered directly into g_r
    apply_kernel<true><<<PB, APPLY_THREADS, SBYTES>>>(theta, px_, slices, pr, nullptr);
    // p = r; Ap = 0; rr0
    init_r_kernel<<<VGRID, VTHREADS>>>();

    for (int it = 0; it < NIT - 1; it++) {
        // Ap = AtA(p); pAp = sum(s^2)
        apply_kernel<false><<<PB, APPLY_THREADS, SBYTES>>>(theta, pp, nullptr, pAp, ppAp + it);
        fused_update_kernel<<<VGRID, VTHREADS>>>(it);
    }
    // Final iteration: only pAp (no Ap scatter, no r update needed)
    apply_dot_kernel<<<PB, APPLY_THREADS>>>(theta, pp, ppAp + (NIT - 1));
    final_kernel<<<VGRID, VTHREADS>>>((float4*)d_out);
}